// round 6
// baseline (speedup 1.0000x reference)
#include <cuda_runtime.h>

#define N 4096
#define NITERS 300
#define NBLK 148
#define TPB 1024

__device__ float  d_B[(size_t)N * N];   // raw distances, 64MB, L2-resident
__device__ float  d_F[N];
__device__ float  d_G2[2][N];           // double-buffered lagged G
__device__ float  d_S2[2][N];           // double-buffered column sums
__device__ double d_csum;
__device__ double d_emd;
__device__ float  d_k;                  // log2(e)/eps
__device__ unsigned int g_bar;
__device__ unsigned int g_epoch;

__device__ __forceinline__ float ex2f(float x) {
    float y;
    asm("ex2.approx.ftz.f32 %0, %1;" : "=f"(y) : "f"(x));
    return y;
}

// ---------------------------------------------------------------- init
__global__ void k_init() {
    d_csum  = 0.0;
    d_emd   = 0.0;
    g_bar   = 0u;
    g_epoch = 0u;
}

// ---------------------------------------------------------------- build C + csum; init state
__global__ void k_build(const float* __restrict__ x, const float* __restrict__ y) {
    __shared__ float sred[8];
    int i = blockIdx.x;
    float x0 = x[3 * i], x1 = x[3 * i + 1], x2 = x[3 * i + 2];
    float xx = x0 * x0 + x1 * x1 + x2 * x2;
    float acc = 0.0f;
    for (int j = threadIdx.x; j < N; j += 256) {
        float y0 = y[3 * j], y1 = y[3 * j + 1], y2 = y[3 * j + 2];
        float yy  = y0 * y0 + y1 * y1 + y2 * y2;
        float dot = x0 * y0 + x1 * y1 + x2 * y2;
        float d2  = xx + yy - 2.0f * dot;
        float c   = sqrtf(fmaxf(d2, 0.0f) + 1e-12f);
        d_B[(size_t)i * N + j] = c;
        acc += c;
    }
    for (int o = 16; o; o >>= 1) acc += __shfl_down_sync(0xffffffffu, acc, o);
    if ((threadIdx.x & 31) == 0) sred[threadIdx.x >> 5] = acc;
    __syncthreads();
    if (threadIdx.x < 8) {
        acc = sred[threadIdx.x];
        for (int o = 4; o; o >>= 1) acc += __shfl_down_sync(0xffu, acc, o);
        if (threadIdx.x == 0) atomicAdd(&d_csum, (double)acc);
    }
    if (threadIdx.x == 0) {
        d_F[i] = 0.0f;
        d_G2[0][i] = 0.0f;  d_G2[1][i] = 0.0f;
        d_S2[0][i] = 0.0f;  d_S2[1][i] = 1.0f;   // log2(1)=0 -> first f-pass sees G=0
    }
}

// ---------------------------------------------------------------- eps -> k
__global__ void k_eps() {
    double mean = d_csum / ((double)N * (double)N);
    d_k = (float)(1.4426950408889634 / (0.02 * mean));
}

// ---------------------------------------------------------------- grid barrier (no membar/IVALL)
__device__ __forceinline__ void gsync(unsigned int& ep) {
    __syncthreads();
    if (threadIdx.x == 0) {
        unsigned int t;
        asm volatile("atom.add.release.gpu.u32 %0, [%1], 1;"
                     : "=r"(t) : "l"(&g_bar) : "memory");
        if (t == NBLK - 1) {
            g_bar = 0u;
            asm volatile("st.release.gpu.u32 [%0], %1;"
                         :: "l"(&g_epoch), "r"(ep + 1u) : "memory");
        } else {
            unsigned int v;
            do {
                asm volatile("ld.acquire.gpu.u32 %0, [%1];"
                             : "=r"(v) : "l"(&g_epoch) : "memory");
            } while (v == ep);
        }
    }
    ep++;
    __syncthreads();
}

// ---------------------------------------------------------------- persistent Sinkhorn + final P*C
__global__ void __launch_bounds__(TPB, 1) k_persist(float* __restrict__ out) {
    __shared__ float sV[N];
    __shared__ float sred[32];
    const int tid = threadIdx.x;
    const int bid = blockIdx.x;
    const int wid = tid >> 5;
    const int ln  = tid & 31;
    const float k  = d_k;
    const float kn = -k;
    const int frow = bid + NBLK * wid;                  // f-pass row (valid if < N)
    const int c4   = tid * 4;                           // g-pass column group
    const bool own = ((tid * NBLK) >> 10) == bid;       // unique owner block of group tid
    const int r0 = (bid * N) / NBLK, r1 = ((bid + 1) * N) / NBLK;   // g-pass row stripe
    unsigned int ep = 0u;

    for (int it = 0; it < NITERS; it++) {
        const int p = it & 1;
        const float* Gr = d_G2[p];       // lagged G (= G^{(t-1)})
        float*       Gw = d_G2[p ^ 1];
        const float* Sr = d_S2[p ^ 1];   // S_{t-1}: brings G current
        float*       Sw = d_S2[p];       // accumulated this iteration

        // ---- f phase: sV[j] = G^{(t)}_j; rows F_i <- F_i - log2(sum_j 2^(G_j + F_i - kB - 12))
        for (int j = tid; j < N; j += TPB)
            sV[j] = __ldcg(&Gr[j]) - log2f(__ldcg(&Sr[j]));
        if (own) {   // Sw buffer is dead (last read one iteration ago) -> zero my group
            __stcg(&Sw[c4 + 0], 0.0f); __stcg(&Sw[c4 + 1], 0.0f);
            __stcg(&Sw[c4 + 2], 0.0f); __stcg(&Sw[c4 + 3], 0.0f);
        }
        __syncthreads();
        if (frow < N) {
            const float Fi = __ldcg(&d_F[frow]);
            const float c  = Fi - 12.0f;
            const float4* Br = (const float4*)(d_B + (size_t)frow * N);
            const float4* V4 = (const float4*)sV;
            float s0 = 0.f, s1 = 0.f, s2 = 0.f, s3 = 0.f;
#pragma unroll 8
            for (int t = ln; t < N / 4; t += 32) {
                float4 b = Br[t];
                float4 g = V4[t];
                s0 += ex2f(fmaf(kn, b.x, g.x + c));
                s1 += ex2f(fmaf(kn, b.y, g.y + c));
                s2 += ex2f(fmaf(kn, b.z, g.z + c));
                s3 += ex2f(fmaf(kn, b.w, g.w + c));
            }
            float s = (s0 + s1) + (s2 + s3);
            for (int o = 16; o; o >>= 1) s += __shfl_down_sync(0xffffffffu, s, o);
            if (ln == 0) __stcg(&d_F[frow], Fi - log2f(s));
        }
        gsync(ep);

        // ---- g phase (row-major): S_j += sum_{i in stripe} 2^(F_i + G_j - kB_ij - 12)
        for (int i = tid; i < N; i += TPB) sV[i] = __ldcg(&d_F[i]);
        float gq0 = __ldcg(&Gr[c4 + 0]) - log2f(__ldcg(&Sr[c4 + 0]));
        float gq1 = __ldcg(&Gr[c4 + 1]) - log2f(__ldcg(&Sr[c4 + 1]));
        float gq2 = __ldcg(&Gr[c4 + 2]) - log2f(__ldcg(&Sr[c4 + 2]));
        float gq3 = __ldcg(&Gr[c4 + 3]) - log2f(__ldcg(&Sr[c4 + 3]));
        if (own) {   // commit current G for next iteration's readers (they read Gw after gsync)
            __stcg(&Gw[c4 + 0], gq0); __stcg(&Gw[c4 + 1], gq1);
            __stcg(&Gw[c4 + 2], gq2); __stcg(&Gw[c4 + 3], gq3);
        }
        const float g0 = gq0 - 12.0f, g1 = gq1 - 12.0f;
        const float g2 = gq2 - 12.0f, g3 = gq3 - 12.0f;
        __syncthreads();
        {
            const float4* B4 = (const float4*)d_B;
            float a0 = 0.f, a1 = 0.f, a2 = 0.f, a3 = 0.f;
            int i = r0;
            for (; i + 2 <= r1; i += 2) {
                float4 b0 = B4[(size_t)i * (N / 4) + tid];
                float4 b1 = B4[(size_t)(i + 1) * (N / 4) + tid];
                float Fa = sV[i], Fb = sV[i + 1];
                a0 += ex2f(fmaf(kn, b0.x, Fa + g0));
                a1 += ex2f(fmaf(kn, b0.y, Fa + g1));
                a2 += ex2f(fmaf(kn, b0.z, Fa + g2));
                a3 += ex2f(fmaf(kn, b0.w, Fa + g3));
                a0 += ex2f(fmaf(kn, b1.x, Fb + g0));
                a1 += ex2f(fmaf(kn, b1.y, Fb + g1));
                a2 += ex2f(fmaf(kn, b1.z, Fb + g2));
                a3 += ex2f(fmaf(kn, b1.w, Fb + g3));
            }
            if (i < r1) {
                float4 b0 = B4[(size_t)i * (N / 4) + tid];
                float Fa = sV[i];
                a0 += ex2f(fmaf(kn, b0.x, Fa + g0));
                a1 += ex2f(fmaf(kn, b0.y, Fa + g1));
                a2 += ex2f(fmaf(kn, b0.z, Fa + g2));
                a3 += ex2f(fmaf(kn, b0.w, Fa + g3));
            }
            atomicAdd(&Sw[c4 + 0], a0);
            atomicAdd(&Sw[c4 + 1], a1);
            atomicAdd(&Sw[c4 + 2], a2);
            atomicAdd(&Sw[c4 + 3], a3);
        }
        gsync(ep);
    }

    // ---- final: sum_ij P_ij * C_ij,  P = 2^(F_i + G_j - kB - 24), C = B
    {
        const int pf = NITERS & 1;                 // = 0
        const float* Gr = d_G2[pf];
        const float* Sr = d_S2[pf ^ 1];
        for (int j = tid; j < N; j += TPB)
            sV[j] = __ldcg(&Gr[j]) - log2f(__ldcg(&Sr[j]));
        __syncthreads();
        float s = 0.f;
        if (frow < N) {
            const float c = __ldcg(&d_F[frow]) - 24.0f;
            const float4* Br = (const float4*)(d_B + (size_t)frow * N);
            const float4* V4 = (const float4*)sV;
            float a0 = 0.f, a1 = 0.f, a2 = 0.f, a3 = 0.f;
#pragma unroll 8
            for (int t = ln; t < N / 4; t += 32) {
                float4 b = Br[t];
                float4 g = V4[t];
                a0 = fmaf(ex2f(fmaf(kn, b.x, g.x + c)), b.x, a0);
                a1 = fmaf(ex2f(fmaf(kn, b.y, g.y + c)), b.y, a1);
                a2 = fmaf(ex2f(fmaf(kn, b.z, g.z + c)), b.z, a2);
                a3 = fmaf(ex2f(fmaf(kn, b.w, g.w + c)), b.w, a3);
            }
            s = (a0 + a1) + (a2 + a3);
            for (int o = 16; o; o >>= 1) s += __shfl_down_sync(0xffffffffu, s, o);
        }
        if (ln == 0) sred[wid] = s;
        __syncthreads();
        if (tid < 32) {
            s = sred[tid];
            for (int o = 16; o; o >>= 1) s += __shfl_down_sync(0xffffffffu, s, o);
            if (tid == 0) atomicAdd(&d_emd, (double)s);
        }
    }
    gsync(ep);
    if (bid == 0 && tid == 0) out[0] = (float)__ldcg((const double*)&d_emd);
}

// ---------------------------------------------------------------- launch
extern "C" void kernel_launch(void* const* d_in, const int* in_sizes, int n_in,
                              void* d_out, int out_size) {
    const float* x = (const float*)d_in[0];
    const float* y = (const float*)d_in[1];
    float* out = (float*)d_out;

    k_init<<<1, 1>>>();
    k_build<<<N, 256>>>(x, y);
    k_eps<<<1, 1>>>();
    k_persist<<<NBLK, TPB>>>(out);
}